// round 11
// baseline (speedup 1.0000x reference)
#include <cuda_runtime.h>
#include <cuda_fp16.h>
#include <cstdint>
#include <cstddef>

#define B_ 2
#define H_ 16
#define L_ 2048
#define S_ 2048
#define D_ 64
#define TR 16
#define SK 128
#define NTHREADS 512

// fp16 copy of values (scratch; __device__ global per allocation rules)
__device__ __half g_v16[(size_t)B_ * S_ * H_ * D_];

__global__ void convert_v_kernel(const float* __restrict__ v) {
    int i = blockIdx.x * blockDim.x + threadIdx.x;   // over float4s
    const float4* v4 = (const float4*)v;
    float4 f = v4[i];
    __half2* dst = (__half2*)g_v16;
    dst[2 * i]     = __floats2half2_rn(f.x, f.y);
    dst[2 * i + 1] = __floats2half2_rn(f.z, f.w);
}

// ---- smem layout ----
// A region: 2 buffers x 3 tiles (mask/ones, e-hat, e-hat^2), each 16 x A_STRIDE halves
#define A_STRIDE 136                       // halves: 272B rows -> conflict-free ldmatrix
#define ATILE (TR * A_STRIDE)              // 2176 halves per tile
#define ABUF  (3 * ATILE)                  // 6528 halves per buffer
#define V_STRIDE 72                        // halves: 144B rows -> conflict-free ldmatrix.trans
#define OFF_A   0
#define OFF_V   (2 * ABUF * 2)             // 26112 bytes
#define VBUF_B  (SK * V_STRIDE * 2)        // 18432 bytes per V buffer
#define OFF_DEN (OFF_V + 2 * VBUF_B)       // 62976
#define SMEM_BYTES (OFF_DEN + 256)         // ~63KB -> 2 CTAs/SM (reg-capped anyway)

#define ONES16 0x3C003C00u                 // __half2(1.0, 1.0)

__device__ __forceinline__ uint32_t h2u(__half2 h) { return *reinterpret_cast<uint32_t*>(&h); }
__device__ __forceinline__ __half2 u2h(uint32_t u) { return *reinterpret_cast<__half2*>(&u); }

__global__ void __launch_bounds__(NTHREADS, 2)
attn_kernel(const float* __restrict__ scores, float* __restrict__ out) {
    extern __shared__ char smem[];
    float* s_rd = (float*)(smem + OFF_DEN);        // 1/den per row
    float* s_s1 = (float*)(smem + OFF_DEN + 64);   // 16/Z per row
    float* s_s2 = (float*)(smem + OFF_DEN + 128);  // 128/Z^2 per row
    float* sumbuf = (float*)(smem + OFF_V);        // reused after last MMA

    const int l0 = blockIdx.x * TR;
    const int bh = blockIdx.y;          // b*H + h
    const int b  = bh >> 4;
    const int h  = bh & 15;

    const int tid  = threadIdx.x;
    const int wid  = tid >> 5;
    const int lane = tid & 31;

    const uint32_t As_u = (uint32_t)__cvta_generic_to_shared(smem + OFF_A);
    const uint32_t Vh_u = (uint32_t)__cvta_generic_to_shared(smem + OFF_V);
    const __half* vbase = g_v16 + ((size_t)b * S_ * H_ + h) * D_;
    const int cdiag = l0 >> 7;          // last (and only partially-masked) MMA chunk
    const int lrow  = l0 + wid;         // this warp's row

    // ---- prefetch V chunk 0 ----
    {
        #pragma unroll
        for (int i = 0; i < 2; ++i) {
            int idx = tid + i * NTHREADS;
            int r = idx >> 3, q = idx & 7;
            const void* src = (const void*)(vbase + (size_t)r * (H_ * D_) + q * 8);
            uint32_t dst = Vh_u + r * (V_STRIDE * 2) + q * 16;
            asm volatile("cp.async.cg.shared.global [%0], [%1], 16;\n" :: "r"(dst), "l"(src) : "memory");
        }
        asm volatile("cp.async.commit_group;\n" ::: "memory");
    }

    // warp w streams row w of scores; one float4 per lane per 128-chunk
    const float4* grow4 = (const float4*)(scores + ((size_t)bh * L_ + lrow) * S_);

    const int kh = wid >> 2;             // k-quarter 0..3
    const int nq = wid & 3;              // n-quarter 0..3
    const int n0 = nq * 16;
    const int ar = lane & 15;
    const int ac = (lane >> 4) * 8;
    const int brow = lane & 15;
    const int bcol = n0 + (lane >> 4) * 8;

    float z = 0.f, E1 = 0.f, E2 = 0.f;
    // accumulators: P = ones-term, X1 = e-hat term, X2 = e-hat^2 term
    float p0=0.f,p1=0.f,p2=0.f,p3=0.f,p4=0.f,p5=0.f,p6=0.f,p7=0.f;
    float x10=0.f,x11=0.f,x12=0.f,x13=0.f,x14=0.f,x15=0.f,x16=0.f,x17=0.f;
    float x20=0.f,x21=0.f,x22=0.f,x23=0.f,x24=0.f,x25=0.f,x26=0.f,x27=0.f;

    float4 cur = grow4[lane];           // chunk 0 scores

    for (int c = 0; c <= cdiag; ++c) {
        const int cb = c & 1;
        const bool dg = (c == cdiag);
        const uint32_t abuf = As_u + cb * (ABUF * 2);
        const uint32_t vbuf = Vh_u + cb * VBUF_B;

        // prefetch next chunk's scores early (used by next MMA chunk or tail)
        float4 nxt;
        if (c < 15) nxt = grow4[lane + 32 * (c + 1)];

        // ---- A-compute: e = exp(score); tiles e-hat and e-hat^2 (+ mask tile on diag) ----
        {
            float e0 = __expf(cur.x), e1 = __expf(cur.y), e2 = __expf(cur.z), e3 = __expf(cur.w);
            z += (e0 + e1) + (e2 + e3);
            float h0 = e0 * 0.0625f, h1 = e1 * 0.0625f, h2 = e2 * 0.0625f, h3 = e3 * 0.0625f;
            uint2* a_st = (uint2*)(smem + OFF_A) + cb * (ABUF / 4) + wid * (A_STRIDE / 4) + lane;
            if (dg) {
                int sb = c * SK + lane * 4;
                float m0 = (sb + 0 <= lrow) ? 1.f : 0.f;
                float m1 = (sb + 1 <= lrow) ? 1.f : 0.f;
                float m2 = (sb + 2 <= lrow) ? 1.f : 0.f;
                float m3 = (sb + 3 <= lrow) ? 1.f : 0.f;
                h0 *= m0; h1 *= m1; h2 *= m2; h3 *= m3;
                uint2 mu;
                mu.x = h2u(__floats2half2_rn(m0, m1));
                mu.y = h2u(__floats2half2_rn(m2, m3));
                a_st[0] = mu;                         // tile 0: mask/ones
            }
            __half2 q01 = __floats2half2_rn(h0, h1);
            __half2 q23 = __floats2half2_rn(h2, h3);
            __half2 r01 = __floats2half2_rn(h0 * h0, h1 * h1);
            __half2 r23 = __floats2half2_rn(h2 * h2, h3 * h3);
            float2 fq01 = __half22float2(q01), fq23 = __half22float2(q23);
            float2 fr01 = __half22float2(r01), fr23 = __half22float2(r23);
            E1 += (fq01.x + fq01.y) + (fq23.x + fq23.y);
            E2 += (fr01.x + fr01.y) + (fr23.x + fr23.y);
            uint2 qu; qu.x = h2u(q01); qu.y = h2u(q23);
            uint2 ru; ru.x = h2u(r01); ru.y = h2u(r23);
            a_st[ATILE / 4]     = qu;                 // tile 1: e-hat
            a_st[2 * ATILE / 4] = ru;                 // tile 2: e-hat^2
        }

        asm volatile("cp.async.wait_group 0;\n" ::: "memory");   // V chunk c resident
        __syncthreads();                                         // tiles visible; prev MMA done

        if (c + 1 <= cdiag) {
            const int s1v = (c + 1) * SK;
            const uint32_t dstb = Vh_u + ((c + 1) & 1) * VBUF_B;
            #pragma unroll
            for (int i = 0; i < 2; ++i) {
                int idx = tid + i * NTHREADS;
                int r = idx >> 3, q = idx & 7;
                const void* src = (const void*)(vbase + (size_t)(s1v + r) * (H_ * D_) + q * 8);
                uint32_t dst = dstb + r * (V_STRIDE * 2) + q * 16;
                asm volatile("cp.async.cg.shared.global [%0], [%1], 16;\n" :: "r"(dst), "l"(src) : "memory");
            }
        }
        asm volatile("cp.async.commit_group;\n" ::: "memory");

        // ---- MMA: 3 powers (ones, e-hat, e-hat^2); warp = k-quarter x n-quarter ----
        #pragma unroll
        for (int t = 0; t < 2; ++t) {
            int kk = kh * 2 + t;
            uint32_t a10,a11,a12,a13, a20,a21,a22,a23, b0,b1,b2,b3, o0,o1,o2,o3;
            uint32_t arow = (uint32_t)((ar * A_STRIDE + kk * 16 + ac) * 2);
            asm volatile("ldmatrix.sync.aligned.m8n8.x4.shared.b16 {%0,%1,%2,%3}, [%4];\n"
                         : "=r"(a10), "=r"(a11), "=r"(a12), "=r"(a13)
                         : "r"(abuf + ATILE * 2 + arow));
            asm volatile("ldmatrix.sync.aligned.m8n8.x4.shared.b16 {%0,%1,%2,%3}, [%4];\n"
                         : "=r"(a20), "=r"(a21), "=r"(a22), "=r"(a23)
                         : "r"(abuf + 2 * ATILE * 2 + arow));
            if (dg) {
                asm volatile("ldmatrix.sync.aligned.m8n8.x4.shared.b16 {%0,%1,%2,%3}, [%4];\n"
                             : "=r"(o0), "=r"(o1), "=r"(o2), "=r"(o3)
                             : "r"(abuf + arow));
            } else {
                o0 = ONES16; o1 = ONES16; o2 = ONES16; o3 = ONES16;
            }
            uint32_t baddr = vbuf + (uint32_t)(((kk * 16 + brow) * V_STRIDE + bcol) * 2);
            asm volatile("ldmatrix.sync.aligned.m8n8.x4.trans.shared.b16 {%0,%1,%2,%3}, [%4];\n"
                         : "=r"(b0), "=r"(b1), "=r"(b2), "=r"(b3) : "r"(baddr));

            asm volatile("mma.sync.aligned.m16n8k16.row.col.f32.f16.f16.f32 "
                         "{%0,%1,%2,%3},{%4,%5,%6,%7},{%8,%9},{%0,%1,%2,%3};\n"
                         : "+f"(p0), "+f"(p1), "+f"(p2), "+f"(p3)
                         : "r"(o0), "r"(o1), "r"(o2), "r"(o3), "r"(b0), "r"(b1));
            asm volatile("mma.sync.aligned.m16n8k16.row.col.f32.f16.f16.f32 "
                         "{%0,%1,%2,%3},{%4,%5,%6,%7},{%8,%9},{%0,%1,%2,%3};\n"
                         : "+f"(p4), "+f"(p5), "+f"(p6), "+f"(p7)
                         : "r"(o0), "r"(o1), "r"(o2), "r"(o3), "r"(b2), "r"(b3));
            asm volatile("mma.sync.aligned.m16n8k16.row.col.f32.f16.f16.f32 "
                         "{%0,%1,%2,%3},{%4,%5,%6,%7},{%8,%9},{%0,%1,%2,%3};\n"
                         : "+f"(x10), "+f"(x11), "+f"(x12), "+f"(x13)
                         : "r"(a10), "r"(a11), "r"(a12), "r"(a13), "r"(b0), "r"(b1));
            asm volatile("mma.sync.aligned.m16n8k16.row.col.f32.f16.f16.f32 "
                         "{%0,%1,%2,%3},{%4,%5,%6,%7},{%8,%9},{%0,%1,%2,%3};\n"
                         : "+f"(x14), "+f"(x15), "+f"(x16), "+f"(x17)
                         : "r"(a10), "r"(a11), "r"(a12), "r"(a13), "r"(b2), "r"(b3));
            asm volatile("mma.sync.aligned.m16n8k16.row.col.f32.f16.f16.f32 "
                         "{%0,%1,%2,%3},{%4,%5,%6,%7},{%8,%9},{%0,%1,%2,%3};\n"
                         : "+f"(x20), "+f"(x21), "+f"(x22), "+f"(x23)
                         : "r"(a20), "r"(a21), "r"(a22), "r"(a23), "r"(b0), "r"(b1));
            asm volatile("mma.sync.aligned.m16n8k16.row.col.f32.f16.f16.f32 "
                         "{%0,%1,%2,%3},{%4,%5,%6,%7},{%8,%9},{%0,%1,%2,%3};\n"
                         : "+f"(x24), "+f"(x25), "+f"(x26), "+f"(x27)
                         : "r"(a20), "r"(a21), "r"(a22), "r"(a23), "r"(b2), "r"(b3));
        }
        cur = nxt;
    }

    // ---- tail: remaining chunks contribute to Z only ----
    {
        int i = cdiag + 1;
        if (i < 16) {
            z += (__expf(cur.x) + __expf(cur.y)) + (__expf(cur.z) + __expf(cur.w));
            ++i;
        }
        #pragma unroll 4
        for (; i < 16; ++i) {
            float4 f = grow4[lane + 32 * i];
            z += (__expf(f.x) + __expf(f.y)) + (__expf(f.z) + __expf(f.w));
        }
    }

    // ---- per-row scalars ----
    #pragma unroll
    for (int o = 16; o; o >>= 1) {
        z  += __shfl_xor_sync(0xffffffffu, z, o);
        E1 += __shfl_xor_sync(0xffffffffu, E1, o);
        E2 += __shfl_xor_sync(0xffffffffu, E2, o);
    }
    if (lane == 0) {
        float t1 = 16.f / z;                 // scales e-hat term
        float t2 = 128.f / (z * z);          // scales e-hat^2 term
        float den = (float)(lrow + 1) + t1 * E1 + t2 * E2;
        s_s1[wid] = t1;
        s_s2[wid] = t2;
        s_rd[wid] = 1.f / den;
    }
    __syncthreads();   // scalars visible; all MMAs done -> V region reusable

    // ---- combine powers, reduce k-quarters, store ----
    const int r1 = lane >> 2;
    float s1a = s_s1[r1],     s2a = s_s2[r1];
    float s1b = s_s1[r1 + 8], s2b = s_s2[r1 + 8];
    float d0 = p0 + s1a * x10 + s2a * x20;
    float d1 = p1 + s1a * x11 + s2a * x21;
    float d2 = p2 + s1b * x12 + s2b * x22;
    float d3 = p3 + s1b * x13 + s2b * x23;
    float d4 = p4 + s1a * x14 + s2a * x24;
    float d5 = p5 + s1a * x15 + s2a * x25;
    float d6 = p6 + s1b * x16 + s2b * x26;
    float d7 = p7 + s1b * x17 + s2b * x27;

    if (kh > 0) {      // warps 4..15 dump combined fragments
        float* p = sumbuf + (wid - 4) * 256 + lane * 8;
        p[0] = d0; p[1] = d1; p[2] = d2; p[3] = d3;
        p[4] = d4; p[5] = d5; p[6] = d6; p[7] = d7;
    }
    __syncthreads();

    if (kh == 0) {     // warps 0..3 reduce the 4 k-parts and store
        #pragma unroll
        for (int p = 0; p < 3; ++p) {
            const float* q = sumbuf + (p * 4 + nq) * 256 + lane * 8;
            d0 += q[0]; d1 += q[1]; d2 += q[2]; d3 += q[3];
            d4 += q[4]; d5 += q[5]; d6 += q[6]; d7 += q[7];
        }
        float rda = s_rd[r1];
        float rdb = s_rd[r1 + 8];
        int col = n0 + (lane & 3) * 2;
        size_t o1 = ((size_t)(b * L_ + l0 + r1) * H_ + h) * D_ + col;
        size_t o2 = ((size_t)(b * L_ + l0 + r1 + 8) * H_ + h) * D_ + col;
        out[o1]         = d0 * rda;
        out[o1 + 1]     = d1 * rda;
        out[o2]         = d2 * rdb;
        out[o2 + 1]     = d3 * rdb;
        out[o1 + 8]     = d4 * rda;
        out[o1 + 9]     = d5 * rda;
        out[o2 + 8]     = d6 * rdb;
        out[o2 + 9]     = d7 * rdb;
    }
}

extern "C" void kernel_launch(void* const* d_in, const int* in_sizes, int n_in,
                              void* d_out, int out_size) {
    // inputs: 0=queries (unused), 1=keys (unused), 2=values [B,S,H,D] f32, 3=scores [B,H,L,S] f32
    const float* values = (const float*)d_in[2];
    const float* scores = (const float*)d_in[3];
    float* out = (float*)d_out;

    convert_v_kernel<<<(B_ * S_ * H_ * D_ / 4) / NTHREADS, NTHREADS>>>(values);

    cudaFuncSetAttribute(attn_kernel, cudaFuncAttributeMaxDynamicSharedMemorySize, SMEM_BYTES);
    dim3 grid(L_ / TR, B_ * H_);
    attn_kernel<<<grid, NTHREADS, SMEM_BYTES>>>(scores, out);
}

// round 12
// speedup vs baseline: 1.0035x; 1.0035x over previous
#include <cuda_runtime.h>
#include <cuda_fp16.h>
#include <cstdint>
#include <cstddef>

#define B_ 2
#define H_ 16
#define L_ 2048
#define S_ 2048
#define D_ 64
#define TR 16
#define SK 128
#define NTHREADS 512

// fp16 copy of values (scratch; __device__ global per allocation rules)
__device__ __half g_v16[(size_t)B_ * S_ * H_ * D_];

__global__ void convert_v_kernel(const float* __restrict__ v) {
    int i = blockIdx.x * blockDim.x + threadIdx.x;   // over float4s
    const float4* v4 = (const float4*)v;
    float4 f = v4[i];
    __half2* dst = (__half2*)g_v16;
    dst[2 * i]     = __floats2half2_rn(f.x, f.y);
    dst[2 * i + 1] = __floats2half2_rn(f.z, f.w);
}

// ---- smem layout ----
// A region: 2 buffers x 3 tiles (mask/ones, e-hat, e-hat^2), each 16 x A_STRIDE halves
#define A_STRIDE 136                       // halves: 272B rows -> conflict-free ldmatrix
#define ATILE (TR * A_STRIDE)              // 2176 halves per tile
#define ABUF  (3 * ATILE)                  // 6528 halves per buffer
#define V_STRIDE 72                        // halves: 144B rows -> conflict-free ldmatrix.trans
#define OFF_A   0
#define OFF_V   (2 * ABUF * 2)             // 26112 bytes
#define VBUF_B  (SK * V_STRIDE * 2)        // 18432 bytes per V buffer
#define OFF_DEN (OFF_V + 2 * VBUF_B)       // 62976
#define SMEM_BYTES (OFF_DEN + 256)         // ~63KB -> 2 CTAs/SM (reg-capped anyway)

#define ONES16 0x3C003C00u                 // __half2(1.0, 1.0)

__device__ __forceinline__ uint32_t h2u(__half2 h) { return *reinterpret_cast<uint32_t*>(&h); }
__device__ __forceinline__ __half2 u2h(uint32_t u) { return *reinterpret_cast<__half2*>(&u); }

__global__ void __launch_bounds__(NTHREADS, 2)
attn_kernel(const float* __restrict__ scores, float* __restrict__ out) {
    extern __shared__ char smem[];
    float* s_rd = (float*)(smem + OFF_DEN);        // 1/den per row
    float* s_s1 = (float*)(smem + OFF_DEN + 64);   // 16/Z per row
    float* s_s2 = (float*)(smem + OFF_DEN + 128);  // 128/Z^2 per row
    float* sumbuf = (float*)(smem + OFF_V);        // reused after last MMA

    const int l0 = blockIdx.x * TR;
    const int bh = blockIdx.y;          // b*H + h
    const int b  = bh >> 4;
    const int h  = bh & 15;

    const int tid  = threadIdx.x;
    const int wid  = tid >> 5;
    const int lane = tid & 31;

    const uint32_t As_u = (uint32_t)__cvta_generic_to_shared(smem + OFF_A);
    const uint32_t Vh_u = (uint32_t)__cvta_generic_to_shared(smem + OFF_V);
    const __half* vbase = g_v16 + ((size_t)b * S_ * H_ + h) * D_;
    const int cdiag = l0 >> 7;          // last (and only partially-masked) MMA chunk
    const int lrow  = l0 + wid;         // this warp's row

    // ---- prefetch V chunk 0 ----
    {
        #pragma unroll
        for (int i = 0; i < 2; ++i) {
            int idx = tid + i * NTHREADS;
            int r = idx >> 3, q = idx & 7;
            const void* src = (const void*)(vbase + (size_t)r * (H_ * D_) + q * 8);
            uint32_t dst = Vh_u + r * (V_STRIDE * 2) + q * 16;
            asm volatile("cp.async.cg.shared.global [%0], [%1], 16;\n" :: "r"(dst), "l"(src) : "memory");
        }
        asm volatile("cp.async.commit_group;\n" ::: "memory");
    }

    // warp w streams row w of scores; one float4 per lane per 128-chunk
    const float4* grow4 = (const float4*)(scores + ((size_t)bh * L_ + lrow) * S_);

    const int kh = wid >> 2;             // k-quarter 0..3
    const int nq = wid & 3;              // n-quarter 0..3
    const int n0 = nq * 16;
    const int ar = lane & 15;
    const int ac = (lane >> 4) * 8;
    const int brow = lane & 15;
    const int bcol = n0 + (lane >> 4) * 8;

    float z = 0.f, E1 = 0.f, E2 = 0.f;
    // accumulators: P = ones-term, X1 = e-hat term, X2 = e-hat^2 term
    float p0=0.f,p1=0.f,p2=0.f,p3=0.f,p4=0.f,p5=0.f,p6=0.f,p7=0.f;
    float x10=0.f,x11=0.f,x12=0.f,x13=0.f,x14=0.f,x15=0.f,x16=0.f,x17=0.f;
    float x20=0.f,x21=0.f,x22=0.f,x23=0.f,x24=0.f,x25=0.f,x26=0.f,x27=0.f;

    float4 cur = grow4[lane];           // chunk 0 scores

    for (int c = 0; c <= cdiag; ++c) {
        const int cb = c & 1;
        const bool dg = (c == cdiag);
        const uint32_t abuf = As_u + cb * (ABUF * 2);
        const uint32_t vbuf = Vh_u + cb * VBUF_B;

        // prefetch next chunk's scores early (used by next MMA chunk or tail)
        float4 nxt;
        if (c < 15) nxt = grow4[lane + 32 * (c + 1)];

        // ---- A-compute: e = exp(score); tiles e-hat and e-hat^2 (+ mask tile on diag) ----
        {
            float e0 = __expf(cur.x), e1 = __expf(cur.y), e2 = __expf(cur.z), e3 = __expf(cur.w);
            z += (e0 + e1) + (e2 + e3);
            float h0 = e0 * 0.0625f, h1 = e1 * 0.0625f, h2 = e2 * 0.0625f, h3 = e3 * 0.0625f;
            uint2* a_st = (uint2*)(smem + OFF_A) + cb * (ABUF / 4) + wid * (A_STRIDE / 4) + lane;
            if (dg) {
                int sb = c * SK + lane * 4;
                float m0 = (sb + 0 <= lrow) ? 1.f : 0.f;
                float m1 = (sb + 1 <= lrow) ? 1.f : 0.f;
                float m2 = (sb + 2 <= lrow) ? 1.f : 0.f;
                float m3 = (sb + 3 <= lrow) ? 1.f : 0.f;
                h0 *= m0; h1 *= m1; h2 *= m2; h3 *= m3;
                uint2 mu;
                mu.x = h2u(__floats2half2_rn(m0, m1));
                mu.y = h2u(__floats2half2_rn(m2, m3));
                a_st[0] = mu;                         // tile 0: mask/ones
            }
            __half2 q01 = __floats2half2_rn(h0, h1);
            __half2 q23 = __floats2half2_rn(h2, h3);
            __half2 r01 = __floats2half2_rn(h0 * h0, h1 * h1);
            __half2 r23 = __floats2half2_rn(h2 * h2, h3 * h3);
            float2 fq01 = __half22float2(q01), fq23 = __half22float2(q23);
            float2 fr01 = __half22float2(r01), fr23 = __half22float2(r23);
            E1 += (fq01.x + fq01.y) + (fq23.x + fq23.y);
            E2 += (fr01.x + fr01.y) + (fr23.x + fr23.y);
            uint2 qu; qu.x = h2u(q01); qu.y = h2u(q23);
            uint2 ru; ru.x = h2u(r01); ru.y = h2u(r23);
            a_st[ATILE / 4]     = qu;                 // tile 1: e-hat
            a_st[2 * ATILE / 4] = ru;                 // tile 2: e-hat^2
        }

        asm volatile("cp.async.wait_group 0;\n" ::: "memory");   // V chunk c resident
        __syncthreads();                                         // tiles visible; prev MMA done

        if (c + 1 <= cdiag) {
            const int s1v = (c + 1) * SK;
            const uint32_t dstb = Vh_u + ((c + 1) & 1) * VBUF_B;
            #pragma unroll
            for (int i = 0; i < 2; ++i) {
                int idx = tid + i * NTHREADS;
                int r = idx >> 3, q = idx & 7;
                const void* src = (const void*)(vbase + (size_t)(s1v + r) * (H_ * D_) + q * 8);
                uint32_t dst = dstb + r * (V_STRIDE * 2) + q * 16;
                asm volatile("cp.async.cg.shared.global [%0], [%1], 16;\n" :: "r"(dst), "l"(src) : "memory");
            }
        }
        asm volatile("cp.async.commit_group;\n" ::: "memory");

        // ---- MMA: 3 powers (ones, e-hat, e-hat^2); warp = k-quarter x n-quarter ----
        #pragma unroll
        for (int t = 0; t < 2; ++t) {
            int kk = kh * 2 + t;
            uint32_t a10,a11,a12,a13, a20,a21,a22,a23, b0,b1,b2,b3, o0,o1,o2,o3;
            uint32_t arow = (uint32_t)((ar * A_STRIDE + kk * 16 + ac) * 2);
            asm volatile("ldmatrix.sync.aligned.m8n8.x4.shared.b16 {%0,%1,%2,%3}, [%4];\n"
                         : "=r"(a10), "=r"(a11), "=r"(a12), "=r"(a13)
                         : "r"(abuf + ATILE * 2 + arow));
            asm volatile("ldmatrix.sync.aligned.m8n8.x4.shared.b16 {%0,%1,%2,%3}, [%4];\n"
                         : "=r"(a20), "=r"(a21), "=r"(a22), "=r"(a23)
                         : "r"(abuf + 2 * ATILE * 2 + arow));
            if (dg) {
                asm volatile("ldmatrix.sync.aligned.m8n8.x4.shared.b16 {%0,%1,%2,%3}, [%4];\n"
                             : "=r"(o0), "=r"(o1), "=r"(o2), "=r"(o3)
                             : "r"(abuf + arow));
            } else {
                o0 = ONES16; o1 = ONES16; o2 = ONES16; o3 = ONES16;
            }
            uint32_t baddr = vbuf + (uint32_t)(((kk * 16 + brow) * V_STRIDE + bcol) * 2);
            asm volatile("ldmatrix.sync.aligned.m8n8.x4.trans.shared.b16 {%0,%1,%2,%3}, [%4];\n"
                         : "=r"(b0), "=r"(b1), "=r"(b2), "=r"(b3) : "r"(baddr));

            asm volatile("mma.sync.aligned.m16n8k16.row.col.f32.f16.f16.f32 "
                         "{%0,%1,%2,%3},{%4,%5,%6,%7},{%8,%9},{%0,%1,%2,%3};\n"
                         : "+f"(p0), "+f"(p1), "+f"(p2), "+f"(p3)
                         : "r"(o0), "r"(o1), "r"(o2), "r"(o3), "r"(b0), "r"(b1));
            asm volatile("mma.sync.aligned.m16n8k16.row.col.f32.f16.f16.f32 "
                         "{%0,%1,%2,%3},{%4,%5,%6,%7},{%8,%9},{%0,%1,%2,%3};\n"
                         : "+f"(p4), "+f"(p5), "+f"(p6), "+f"(p7)
                         : "r"(o0), "r"(o1), "r"(o2), "r"(o3), "r"(b2), "r"(b3));
            asm volatile("mma.sync.aligned.m16n8k16.row.col.f32.f16.f16.f32 "
                         "{%0,%1,%2,%3},{%4,%5,%6,%7},{%8,%9},{%0,%1,%2,%3};\n"
                         : "+f"(x10), "+f"(x11), "+f"(x12), "+f"(x13)
                         : "r"(a10), "r"(a11), "r"(a12), "r"(a13), "r"(b0), "r"(b1));
            asm volatile("mma.sync.aligned.m16n8k16.row.col.f32.f16.f16.f32 "
                         "{%0,%1,%2,%3},{%4,%5,%6,%7},{%8,%9},{%0,%1,%2,%3};\n"
                         : "+f"(x14), "+f"(x15), "+f"(x16), "+f"(x17)
                         : "r"(a10), "r"(a11), "r"(a12), "r"(a13), "r"(b2), "r"(b3));
            asm volatile("mma.sync.aligned.m16n8k16.row.col.f32.f16.f16.f32 "
                         "{%0,%1,%2,%3},{%4,%5,%6,%7},{%8,%9},{%0,%1,%2,%3};\n"
                         : "+f"(x20), "+f"(x21), "+f"(x22), "+f"(x23)
                         : "r"(a20), "r"(a21), "r"(a22), "r"(a23), "r"(b0), "r"(b1));
            asm volatile("mma.sync.aligned.m16n8k16.row.col.f32.f16.f16.f32 "
                         "{%0,%1,%2,%3},{%4,%5,%6,%7},{%8,%9},{%0,%1,%2,%3};\n"
                         : "+f"(x24), "+f"(x25), "+f"(x26), "+f"(x27)
                         : "r"(a20), "r"(a21), "r"(a22), "r"(a23), "r"(b2), "r"(b3));
        }
        cur = nxt;
    }

    // ---- tail: remaining chunks contribute to Z only ----
    {
        int i = cdiag + 1;
        if (i < 16) {
            z += (__expf(cur.x) + __expf(cur.y)) + (__expf(cur.z) + __expf(cur.w));
            ++i;
        }
        #pragma unroll 4
        for (; i < 16; ++i) {
            float4 f = grow4[lane + 32 * i];
            z += (__expf(f.x) + __expf(f.y)) + (__expf(f.z) + __expf(f.w));
        }
    }

    // ---- per-row scalars ----
    #pragma unroll
    for (int o = 16; o; o >>= 1) {
        z  += __shfl_xor_sync(0xffffffffu, z, o);
        E1 += __shfl_xor_sync(0xffffffffu, E1, o);
        E2 += __shfl_xor_sync(0xffffffffu, E2, o);
    }
    if (lane == 0) {
        float t1 = 16.f / z;                 // scales e-hat term
        float t2 = 128.f / (z * z);          // scales e-hat^2 term
        float den = (float)(lrow + 1) + t1 * E1 + t2 * E2;
        s_s1[wid] = t1;
        s_s2[wid] = t2;
        s_rd[wid] = 1.f / den;
    }
    __syncthreads();   // scalars visible; all MMAs done -> V region reusable

    // ---- combine powers, reduce k-quarters, store ----
    const int r1 = lane >> 2;
    float s1a = s_s1[r1],     s2a = s_s2[r1];
    float s1b = s_s1[r1 + 8], s2b = s_s2[r1 + 8];
    float d0 = p0 + s1a * x10 + s2a * x20;
    float d1 = p1 + s1a * x11 + s2a * x21;
    float d2 = p2 + s1b * x12 + s2b * x22;
    float d3 = p3 + s1b * x13 + s2b * x23;
    float d4 = p4 + s1a * x14 + s2a * x24;
    float d5 = p5 + s1a * x15 + s2a * x25;
    float d6 = p6 + s1b * x16 + s2b * x26;
    float d7 = p7 + s1b * x17 + s2b * x27;

    if (kh > 0) {      // warps 4..15 dump combined fragments
        float* p = sumbuf + (wid - 4) * 256 + lane * 8;
        p[0] = d0; p[1] = d1; p[2] = d2; p[3] = d3;
        p[4] = d4; p[5] = d5; p[6] = d6; p[7] = d7;
    }
    __syncthreads();

    if (kh == 0) {     // warps 0..3 reduce the 4 k-parts and store
        #pragma unroll
        for (int p = 0; p < 3; ++p) {
            const float* q = sumbuf + (p * 4 + nq) * 256 + lane * 8;
            d0 += q[0]; d1 += q[1]; d2 += q[2]; d3 += q[3];
            d4 += q[4]; d5 += q[5]; d6 += q[6]; d7 += q[7];
        }
        float rda = s_rd[r1];
        float rdb = s_rd[r1 + 8];
        int col = n0 + (lane & 3) * 2;
        size_t o1 = ((size_t)(b * L_ + l0 + r1) * H_ + h) * D_ + col;
        size_t o2 = ((size_t)(b * L_ + l0 + r1 + 8) * H_ + h) * D_ + col;
        out[o1]         = d0 * rda;
        out[o1 + 1]     = d1 * rda;
        out[o2]         = d2 * rdb;
        out[o2 + 1]     = d3 * rdb;
        out[o1 + 8]     = d4 * rda;
        out[o1 + 9]     = d5 * rda;
        out[o2 + 8]     = d6 * rdb;
        out[o2 + 9]     = d7 * rdb;
    }
}

extern "C" void kernel_launch(void* const* d_in, const int* in_sizes, int n_in,
                              void* d_out, int out_size) {
    // inputs: 0=queries (unused), 1=keys (unused), 2=values [B,S,H,D] f32, 3=scores [B,H,L,S] f32
    const float* values = (const float*)d_in[2];
    const float* scores = (const float*)d_in[3];
    float* out = (float*)d_out;

    convert_v_kernel<<<(B_ * S_ * H_ * D_ / 4) / NTHREADS, NTHREADS>>>(values);

    cudaFuncSetAttribute(attn_kernel, cudaFuncAttributeMaxDynamicSharedMemorySize, SMEM_BYTES);
    dim3 grid(L_ / TR, B_ * H_);
    attn_kernel<<<grid, NTHREADS, SMEM_BYTES>>>(scores, out);
}